// round 9
// baseline (speedup 1.0000x reference)
#include <cuda_runtime.h>
#include <math.h>

// ConvLSTM T=16,B=4,Cin=32,HID=64,H=W=64, 3x3 SAME.
// Fused per-step conv(x)+conv(h)+LSTM pointwise with packed fma.rn.f32x2,
// register-budgeted: acc[8][2] (32 regs) + v[4][3] (24 regs).

#define T_   16
#define B_   4
#define CIN  32
#define HID  64
#define HH   64
#define WW   64
#define ICC  8
#define PROWS 34          // 32 + 2 halo rows
#define PCOLS 34          // 32 + 2 halo cols
#define PPAD  36          // padded col stride (8B-aligned pairs)

#define PATCH_FLOATS (ICC * PROWS * PPAD)
#define W_FLOATS     (ICC * 8 * 9 * 2)
#define SMEM_BYTES   ((PATCH_FLOATS + W_FLOATS) * 4)

typedef unsigned long long ull;

__device__ float g_c[B_ * HID * HH * WW];   // cell state (4 MB)

__device__ __forceinline__ float sigmoidf_(float v) {
    return 1.f / (1.f + __expf(-v));
}
__device__ __forceinline__ void fma2(ull& d, ull a, ull b) {
    asm("fma.rn.f32x2 %0, %1, %2, %0;" : "+l"(d) : "l"(a), "l"(b));
}
__device__ __forceinline__ ull pk2(float lo, float hi) {
    ull r;
    asm("mov.b64 %0, {%1, %2};" : "=l"(r) : "f"(lo), "f"(hi));
    return r;
}
__device__ __forceinline__ float plo(ull v) { return __uint_as_float((unsigned)v); }
__device__ __forceinline__ float phi(ull v) { return __uint_as_float((unsigned)(v >> 32)); }

__global__ __launch_bounds__(256, 2)
void convlstm_step(const float* __restrict__ x_t,     // [B, CIN, H, W]
                   const float* __restrict__ h_prev,  // [B, HID, H, W]
                   const float* __restrict__ w_x2h,   // [4*HID, CIN, 3, 3]
                   const float* __restrict__ w_h2h,   // [4*HID, HID, 3, 3]
                   const float* __restrict__ b_x2h,
                   const float* __restrict__ b_h2h,
                   float* __restrict__ h_out,         // [B, HID, H, W]
                   int first)
{
    extern __shared__ float smem[];
    float* patch = smem;                  // [ICC][PROWS][PPAD]
    float* wdup  = smem + PATCH_FLOATS;   // [ICC][8][9][2] duplicated pairs

    const int tid  = threadIdx.x;
    const int warp = tid >> 5;
    const int lane = tid & 31;
    const int ty   = tid >> 4;            // 0..15 -> rows 2ty, 2ty+1
    const int tx   = tid & 15;            // 0..15 -> cols 2tx, 2tx+1 (one pair)
    const int tile = blockIdx.x;          // 0..3 (2x2 tiles of 32x32)
    const int ty0  = (tile >> 1) * 32;
    const int tx0  = (tile & 1) * 32;
    const int hid_base = blockIdx.y * 2;  // 2 hid channels per block
    const int b = blockIdx.z;

    // acc[l][r]: l = gate*2 + jh, r = row 0/1. Each ull = pixel pair (2tx, 2tx+1).
    ull acc[8][2];
#pragma unroll
    for (int l = 0; l < 8; l++) {
        int oc = (l >> 1) * HID + hid_base + (l & 1);
        float bias = b_x2h[oc] + b_h2h[oc];
        ull bb = pk2(bias, bias);
        acc[l][0] = bb; acc[l][1] = bb;
    }

    const int icTotal = first ? CIN : (CIN + HID);

    for (int ic0 = 0; ic0 < icTotal; ic0 += ICC) {
        const float* src;
        const float* wsrc;
        int wnic, ch;
        if (ic0 < CIN) {
            src = x_t + (size_t)b * CIN * HH * WW;
            wsrc = w_x2h; wnic = CIN; ch = ic0;
        } else {
            src = h_prev + (size_t)b * HID * HH * WW;
            wsrc = w_h2h; wnic = HID; ch = ic0 - CIN;
        }

        // structured patch fill: job = (ic, row), warp handles jobs warp, warp+8, ...
        for (int job = warp; job < ICC * PROWS; job += 8) {
            int ic  = job / PROWS;
            int row = job - ic * PROWS;
            int gy  = ty0 - 1 + row;
            const float* gsrc = src + (size_t)(ch + ic) * HH * WW + gy * WW;
            float* dst = patch + ic * PROWS * PPAD + row * PPAD;
            bool rowok = (unsigned)gy < (unsigned)HH;
#pragma unroll
            for (int c0 = 0; c0 < PCOLS; c0 += 32) {
                int col = c0 + lane;
                if (col < PCOLS) {
                    int gx = tx0 - 1 + col;
                    float v = 0.f;
                    if (rowok && (unsigned)gx < (unsigned)WW) v = gsrc[gx];
                    dst[col] = v;
                }
            }
        }
        // weights: duplicated pairs
        for (int idx = tid; idx < ICC * 8 * 9; idx += 256) {
            int ic = idx / 72;
            int r  = idx - ic * 72;
            int l  = r / 9;
            int k  = r - l * 9;
            int oc = (l >> 1) * HID + hid_base + (l & 1);
            float w = wsrc[((size_t)oc * wnic + ch + ic) * 9 + k];
            wdup[(idx << 1)]     = w;
            wdup[(idx << 1) + 1] = w;
        }
        __syncthreads();

#pragma unroll
        for (int ic = 0; ic < ICC; ic++) {
            // v[r][s]: input rows 2ty+r (r=0..3), pair starting at col 2tx+s (s=0..2)
            ull v[4][3];
            const float* prow = patch + ic * PROWS * PPAD + (2 * ty) * PPAD + 2 * tx;
#pragma unroll
            for (int r = 0; r < 4; r++) {
                ull a = *(const ull*)(prow + r * PPAD);
                ull c = *(const ull*)(prow + r * PPAD + 2);
                v[r][0] = a;
                v[r][2] = c;
                v[r][1] = pk2(phi(a), plo(c));   // odd-offset pair via repack
            }
            const float* wp = wdup + ic * 144;
#pragma unroll
            for (int l = 0; l < 8; l++) {
#pragma unroll
                for (int ky = 0; ky < 3; ky++) {
#pragma unroll
                    for (int kx = 0; kx < 3; kx++) {
                        ull w2 = *(const ull*)(wp + l * 18 + (ky * 3 + kx) * 2);
                        fma2(acc[l][0], v[ky + 0][kx], w2);
                        fma2(acc[l][1], v[ky + 1][kx], w2);
                    }
                }
            }
        }
        __syncthreads();
    }

    // LSTM epilogue: gate order i, f, g, o
#pragma unroll
    for (int jh = 0; jh < 2; jh++) {
        const int hid = hid_base + jh;
#pragma unroll
        for (int r = 0; r < 2; r++) {
            const int y = ty0 + 2 * ty + r;
#pragma unroll
            for (int half = 0; half < 2; half++) {
                const int x = tx0 + 2 * tx + half;
                const size_t off = ((size_t)(b * HID + hid)) * HH * WW
                                 + (size_t)y * WW + x;
                float aI = half ? phi(acc[0 * 2 + jh][r]) : plo(acc[0 * 2 + jh][r]);
                float aF = half ? phi(acc[1 * 2 + jh][r]) : plo(acc[1 * 2 + jh][r]);
                float aG = half ? phi(acc[2 * 2 + jh][r]) : plo(acc[2 * 2 + jh][r]);
                float aO = half ? phi(acc[3 * 2 + jh][r]) : plo(acc[3 * 2 + jh][r]);
                float gi = sigmoidf_(aI);
                float gf = sigmoidf_(aF);
                float gg = tanhf(aG);
                float go = sigmoidf_(aO);
                float cold = first ? 0.f : g_c[off];
                float cn = gf * cold + gi * gg;
                g_c[off]   = cn;
                h_out[off] = go * tanhf(cn);
            }
        }
    }
}

extern "C" void kernel_launch(void* const* d_in, const int* in_sizes, int n_in,
                              void* d_out, int out_size)
{
    const float* x     = (const float*)d_in[0];
    const float* w_x2h = (const float*)d_in[1];
    const float* b_x2h = (const float*)d_in[2];
    const float* w_h2h = (const float*)d_in[3];
    const float* b_h2h = (const float*)d_in[4];
    float* out = (float*)d_out;

    cudaFuncSetAttribute(convlstm_step,
                         cudaFuncAttributeMaxDynamicSharedMemorySize, SMEM_BYTES);

    const size_t x_step = (size_t)B_ * CIN * HH * WW;
    const size_t h_step = (size_t)B_ * HID * HH * WW;

    dim3 grid(4, HID / 2, B_);   // 4 spatial tiles, 32 hid-groups, 4 batch
    for (int t = 0; t < T_; t++) {
        const float* x_t    = x + (size_t)t * x_step;
        const float* h_prev = (t == 0) ? x : out + (size_t)(t - 1) * h_step;
        float* h_out        = out + (size_t)t * h_step;
        convlstm_step<<<grid, 256, SMEM_BYTES>>>(x_t, h_prev, w_x2h, w_h2h,
                                                 b_x2h, b_h2h, h_out, t == 0 ? 1 : 0);
    }
}

// round 11
// speedup vs baseline: 10.4952x; 10.4952x over previous
#include <cuda_runtime.h>
#include <cuda_bf16.h>
#include <math.h>
#include <stdint.h>

// ConvLSTM T=16,B=4,Cin=32,HID=64,H=W=64, 3x3 SAME — warp-level HMMA bf16 hi/lo split.
// Per step, per CTA: gates[128 px, 256 oc] = sum_{icg,tap} A_shift @ B^T (K=16/pass, 3 passes).
// A smem: 264 rows (4 img rows x 66 padded cols) x [16 hi | 16 lo] bf16, stride 80B.
// B smem: per tap 256 oc x [16 hi | 16 lo] bf16, stride 80B, double-buffered cp.async.

#define T_ 16
#define B_ 4
#define CIN 32
#define HID 64
#define HW 4096

#define OFF_BIAS 0
#define OFF_A 1024
#define A_BYTES (264 * 80)            // 21120
#define OFF_B (OFF_A + A_BYTES)       // 22144
#define B_BUF 20480                   // 256 * 80
#define GSTRIDE 264
#define OFF_GATES 1024
#define SMEM_TOTAL (OFF_GATES + 128 * GSTRIDE * 4)   // 136192

__device__ float g_c[B_ * HID * HW];                        // cell state (4 MB)
__device__ __align__(128) unsigned char g_B[54 * 16384];    // split weights (864 KB)

static __device__ __forceinline__ uint32_t s2u(const void* p) {
    uint32_t a;
    asm("{ .reg .u64 t; cvta.to.shared.u64 t, %1; cvt.u32.u64 %0, t; }" : "=r"(a) : "l"(p));
    return a;
}
static __device__ __forceinline__ void ldsm4(unsigned* r, uint32_t addr) {
    asm volatile("ldmatrix.sync.aligned.m8n8.x4.shared.b16 {%0,%1,%2,%3}, [%4];"
                 : "=r"(r[0]), "=r"(r[1]), "=r"(r[2]), "=r"(r[3]) : "r"(addr));
}
static __device__ __forceinline__ void mma16816(float* d, const unsigned* a, const unsigned* b) {
    asm volatile("mma.sync.aligned.m16n8k16.row.col.f32.bf16.bf16.f32 "
                 "{%0,%1,%2,%3}, {%4,%5,%6,%7}, {%8,%9}, {%0,%1,%2,%3};"
                 : "+f"(d[0]), "+f"(d[1]), "+f"(d[2]), "+f"(d[3])
                 : "r"(a[0]), "r"(a[1]), "r"(a[2]), "r"(a[3]), "r"(b[0]), "r"(b[1]));
}
static __device__ __forceinline__ float sigf(float x) {
    return 1.f / (1.f + __expf(-x));
}
static __device__ __forceinline__ uint32_t pkbf(float v0, float v1) {
    __nv_bfloat162 t = __floats2bfloat162_rn(v0, v1);
    return *(uint32_t*)&t;
}

// ---------------- weight prep: split fp32 -> bf16 hi/lo ----------------
// g_B tile (icg*9+tap): 256 oc rows x 64B: bytes [0,32)=hi ch0..15, [32,64)=lo ch0..15
__global__ void prep_kernel(const float* __restrict__ w_x2h, const float* __restrict__ w_h2h) {
    const int icg = blockIdx.x / 9, tap = blockIdx.x % 9;
    const int oc = threadIdx.x;
    uint32_t* dst = (uint32_t*)(g_B + (size_t)blockIdx.x * 16384 + oc * 64);
#pragma unroll
    for (int cp = 0; cp < 8; cp++) {
        float w0, w1;
        if (icg < 2) {
            int ic = icg * 16 + 2 * cp;
            w0 = w_x2h[((size_t)oc * CIN + ic) * 9 + tap];
            w1 = w_x2h[((size_t)oc * CIN + ic + 1) * 9 + tap];
        } else {
            int ic = (icg - 2) * 16 + 2 * cp;
            w0 = w_h2h[((size_t)oc * HID + ic) * 9 + tap];
            w1 = w_h2h[((size_t)oc * HID + ic + 1) * 9 + tap];
        }
        __nv_bfloat16 h0 = __float2bfloat16(w0);
        __nv_bfloat16 h1 = __float2bfloat16(w1);
        float l0 = w0 - __bfloat162float(h0);
        float l1 = w1 - __bfloat162float(h1);
        dst[cp]     = ((uint32_t)__bfloat16_as_ushort(h1) << 16) | __bfloat16_as_ushort(h0);
        dst[8 + cp] = pkbf(l0, l1);
    }
}

// ---------------- per-timestep kernel ----------------
__global__ __launch_bounds__(512)
void step_kernel(const float* __restrict__ x_t,     // [B,CIN,64,64]
                 const float* __restrict__ h_prev,  // [B,HID,64,64]
                 const float* __restrict__ b_x2h,
                 const float* __restrict__ b_h2h,
                 float* __restrict__ h_out,         // [B,HID,64,64]
                 int first)
{
    extern __shared__ unsigned char sm[];
    const uint32_t smb = s2u(sm);
    const int tid = threadIdx.x;
    const int wid = tid >> 5, lane = tid & 31;
    const int mi = wid & 3, ni = wid >> 2;     // warp tile: 32 px x 64 oc (gate ni)
    const int y0 = blockIdx.x * 2;
    const int b  = blockIdx.y;

    float* sbias = (float*)(sm + OFF_BIAS);
    if (tid < 256) sbias[tid] = b_x2h[tid] + b_h2h[tid];

    // per-lane ldmatrix base addresses
    const int idxl = lane & 7, q = lane >> 3;
    uint32_t baseA[2];
#pragma unroll
    for (int mt = 0; mt < 2; mt++) {
        int px = mi * 32 + mt * 16 + ((q & 1) << 3) + idxl;
        int arow = ((px >> 6) + 1) * 66 + (px & 63) + 1;
        baseA[mt] = smb + OFF_A + arow * 80 + ((q >> 1) << 4);
    }
    uint32_t baseB[4];
#pragma unroll
    for (int p = 0; p < 4; p++) {
        int oc = ni * 64 + p * 16 + ((q >> 1) << 3) + idxl;
        baseB[p] = oc * 80 + ((q & 1) << 4);
    }

    float acc[2][8][4];
#pragma unroll
    for (int mt = 0; mt < 2; mt++)
#pragma unroll
        for (int t8 = 0; t8 < 8; t8++)
#pragma unroll
            for (int k = 0; k < 4; k++) acc[mt][t8][k] = 0.f;

    const int NG = first ? 2 : 6;

#define ISSUE_CP(icg_, tap_, buf_) do {                                              \
    const char* gsrc = (const char*)g_B + ((size_t)((icg_) * 9 + (tap_))) * 16384;   \
    _Pragma("unroll")                                                                \
    for (int i2 = 0; i2 < 2; i2++) {                                                 \
        int ii = tid + i2 * 512;                                                     \
        int oc_ = ii >> 2, j_ = ii & 3;                                              \
        uint32_t dsts = smb + OFF_B + (buf_) * B_BUF + oc_ * 80 + j_ * 16;           \
        asm volatile("cp.async.cg.shared.global [%0], [%1], 16;"                     \
                     :: "r"(dsts), "l"(gsrc + oc_ * 64 + j_ * 16) : "memory");       \
    }                                                                                \
    asm volatile("cp.async.commit_group;" ::: "memory");                             \
} while (0)

    for (int icg = 0; icg < NG; icg++) {
        __syncthreads();   // A safe to overwrite
        // ---- fill A: 264 halo-padded pixel rows, 16 ch hi|lo ----
        {
            const float* srcb = (icg < 2)
                ? x_t    + ((size_t)b * CIN + icg * 16) * HW
                : h_prev + ((size_t)b * HID + (icg - 2) * 16) * HW;
            for (int p = tid; p < 264; p += 512) {
                int rr = p / 66, cc = p - rr * 66;
                int r_img = y0 - 1 + rr;
                bool ok = (cc >= 1) && (cc <= 64) && ((unsigned)r_img < 64u);
                const float* gp = srcb + r_img * 64 + (cc - 1);
                uint32_t* dst = (uint32_t*)(sm + OFF_A + p * 80);
#pragma unroll
                for (int cp = 0; cp < 8; cp++) {
                    float v0 = ok ? gp[(2 * cp) * HW] : 0.f;
                    float v1 = ok ? gp[(2 * cp + 1) * HW] : 0.f;
                    __nv_bfloat16 h0 = __float2bfloat16(v0);
                    __nv_bfloat16 h1 = __float2bfloat16(v1);
                    float l0 = v0 - __bfloat162float(h0);
                    float l1 = v1 - __bfloat162float(h1);
                    dst[cp]     = ((uint32_t)__bfloat16_as_ushort(h1) << 16) | __bfloat16_as_ushort(h0);
                    dst[8 + cp] = pkbf(l0, l1);
                }
            }
        }
        ISSUE_CP(icg, 0, 0);

        for (int tap = 0; tap < 9; tap++) {
            const int buf = tap & 1;
            asm volatile("cp.async.wait_group 0;" ::: "memory");
            __syncthreads();                       // B[buf] visible; buf^1 free
            if (tap < 8) ISSUE_CP(icg, tap + 1, buf ^ 1);

            const int dy = tap / 3 - 1, dx = tap % 3 - 1;
            const int ash = (dy * 66 + dx) * 80;
            unsigned ahi[2][4], alo[2][4];
            ldsm4(ahi[0], baseA[0] + ash);
            ldsm4(ahi[1], baseA[1] + ash);
            ldsm4(alo[0], baseA[0] + ash + 32);
            ldsm4(alo[1], baseA[1] + ash + 32);

            const uint32_t bb = smb + OFF_B + buf * B_BUF;
#pragma unroll
            for (int half = 0; half < 2; half++) {
                unsigned bh[2][4], bl[2][4];
                ldsm4(bh[0], bb + baseB[2 * half]);
                ldsm4(bh[1], bb + baseB[2 * half + 1]);
                ldsm4(bl[0], bb + baseB[2 * half] + 32);
                ldsm4(bl[1], bb + baseB[2 * half + 1] + 32);
#pragma unroll
                for (int mt = 0; mt < 2; mt++) {
#pragma unroll
                    for (int tt = 0; tt < 4; tt++) {
                        float* d = acc[mt][half * 4 + tt];
                        const unsigned* fh = &bh[tt >> 1][(tt & 1) * 2];
                        const unsigned* fl = &bl[tt >> 1][(tt & 1) * 2];
                        mma16816(d, ahi[mt], fh);   // hi*hi
                        mma16816(d, alo[mt], fh);   // lo*hi
                        mma16816(d, ahi[mt], fl);   // hi*lo
                    }
                }
            }
        }
    }

    // ---- store accumulators to gates smem ----
    __syncthreads();
    float* gates = (float*)(sm + OFF_GATES);
    {
        const int tg = lane >> 2, t4 = lane & 3;
#pragma unroll
        for (int mt = 0; mt < 2; mt++) {
#pragma unroll
            for (int t8 = 0; t8 < 8; t8++) {
                int px0 = mi * 32 + mt * 16 + tg;
                int oc0 = ni * 64 + t8 * 8 + t4 * 2;
                gates[px0 * GSTRIDE + oc0]           = acc[mt][t8][0];
                gates[px0 * GSTRIDE + oc0 + 1]       = acc[mt][t8][1];
                gates[(px0 + 8) * GSTRIDE + oc0]     = acc[mt][t8][2];
                gates[(px0 + 8) * GSTRIDE + oc0 + 1] = acc[mt][t8][3];
            }
        }
    }
    __syncthreads();

    // ---- LSTM pointwise ----
    for (int idx = tid; idx < 128 * 64; idx += 512) {
        const int hid = idx >> 7;
        const int px  = idx & 127;
        const int y = y0 + (px >> 6), x = px & 63;
        const float* gp = gates + px * GSTRIDE;
        float ai = gp[hid]       + sbias[hid];
        float af = gp[64 + hid]  + sbias[64 + hid];
        float ag = gp[128 + hid] + sbias[128 + hid];
        float ao = gp[192 + hid] + sbias[192 + hid];
        const size_t off = (((size_t)b * HID + hid) * 64 + y) * 64 + x;
        float gi = sigf(ai), gf = sigf(af), gg = tanhf(ag), go = sigf(ao);
        float cprev = first ? 0.f : g_c[off];
        float cn = gf * cprev + gi * gg;
        g_c[off]   = cn;
        h_out[off] = go * tanhf(cn);
    }
}

extern "C" void kernel_launch(void* const* d_in, const int* in_sizes, int n_in,
                              void* d_out, int out_size)
{
    const float* x     = (const float*)d_in[0];
    const float* w_x2h = (const float*)d_in[1];
    const float* b_x2h = (const float*)d_in[2];
    const float* w_h2h = (const float*)d_in[3];
    const float* b_h2h = (const float*)d_in[4];
    float* out = (float*)d_out;

    cudaFuncSetAttribute(step_kernel,
                         cudaFuncAttributeMaxDynamicSharedMemorySize, SMEM_TOTAL);

    prep_kernel<<<54, 256>>>(w_x2h, w_h2h);

    const size_t x_step = (size_t)B_ * CIN * HW;
    const size_t h_step = (size_t)B_ * HID * HW;
    dim3 grid(32, B_);
    for (int t = 0; t < T_; t++) {
        const float* x_t    = x + (size_t)t * x_step;
        const float* h_prev = (t == 0) ? x : out + (size_t)(t - 1) * h_step;
        float* h_out        = out + (size_t)t * h_step;
        step_kernel<<<grid, 512, SMEM_TOTAL>>>(x_t, h_prev, b_x2h, b_h2h,
                                               h_out, t == 0 ? 1 : 0);
    }
}

// round 13
// speedup vs baseline: 10.7472x; 1.0240x over previous
#include <cuda_runtime.h>
#include <cuda_bf16.h>
#include <math.h>
#include <stdint.h>

// ConvLSTM T=16,B=4,Cin=32,HID=64,H=W=64, 3x3 SAME — warp-level HMMA bf16 hi/lo split.
// R12: term-outer MMA ordering (acc RAW distance 8) + 3-taps-per-barrier B staging.

#define T_ 16
#define B_ 4
#define CIN 32
#define HID 64
#define HW 4096

#define OFF_BIAS 0
#define OFF_A 1024
#define A_BYTES (264 * 80)            // 21120
#define OFF_B (OFF_A + A_BYTES)       // 22144
#define TILE_SM 20480                 // 256 rows * 80B
#define GRP_SM (3 * TILE_SM)          // 61440 (3 taps per group)
#define GSTRIDE 264
#define OFF_GATES 1024
#define SMEM_TOTAL (OFF_B + 2 * GRP_SM)   // 145024

__device__ float g_c[B_ * HID * HW];                        // cell state (4 MB)
__device__ __align__(128) unsigned char g_B[54 * 16384];    // split weights (864 KB)

static __device__ __forceinline__ uint32_t s2u(const void* p) {
    uint32_t a;
    asm("{ .reg .u64 t; cvta.to.shared.u64 t, %1; cvt.u32.u64 %0, t; }" : "=r"(a) : "l"(p));
    return a;
}
static __device__ __forceinline__ void ldsm4(unsigned* r, uint32_t addr) {
    asm volatile("ldmatrix.sync.aligned.m8n8.x4.shared.b16 {%0,%1,%2,%3}, [%4];"
                 : "=r"(r[0]), "=r"(r[1]), "=r"(r[2]), "=r"(r[3]) : "r"(addr));
}
static __device__ __forceinline__ void mma16816(float* d, const unsigned* a, const unsigned* b) {
    asm volatile("mma.sync.aligned.m16n8k16.row.col.f32.bf16.bf16.f32 "
                 "{%0,%1,%2,%3}, {%4,%5,%6,%7}, {%8,%9}, {%0,%1,%2,%3};"
                 : "+f"(d[0]), "+f"(d[1]), "+f"(d[2]), "+f"(d[3])
                 : "r"(a[0]), "r"(a[1]), "r"(a[2]), "r"(a[3]), "r"(b[0]), "r"(b[1]));
}
static __device__ __forceinline__ float sigf(float x) {
    return 1.f / (1.f + __expf(-x));
}
static __device__ __forceinline__ uint32_t pkbf(float v0, float v1) {
    __nv_bfloat162 t = __floats2bfloat162_rn(v0, v1);
    return *(uint32_t*)&t;
}

// ---------------- weight prep: split fp32 -> bf16 hi/lo ----------------
// g_B tile (icg*9+tap): 256 oc rows x 64B: [0,32)=hi ch0..15, [32,64)=lo ch0..15
__global__ void prep_kernel(const float* __restrict__ w_x2h, const float* __restrict__ w_h2h) {
    const int icg = blockIdx.x / 9, tap = blockIdx.x % 9;
    const int oc = threadIdx.x;
    uint32_t* dst = (uint32_t*)(g_B + (size_t)blockIdx.x * 16384 + oc * 64);
#pragma unroll
    for (int cp = 0; cp < 8; cp++) {
        float w0, w1;
        if (icg < 2) {
            int ic = icg * 16 + 2 * cp;
            w0 = w_x2h[((size_t)oc * CIN + ic) * 9 + tap];
            w1 = w_x2h[((size_t)oc * CIN + ic + 1) * 9 + tap];
        } else {
            int ic = (icg - 2) * 16 + 2 * cp;
            w0 = w_h2h[((size_t)oc * HID + ic) * 9 + tap];
            w1 = w_h2h[((size_t)oc * HID + ic + 1) * 9 + tap];
        }
        __nv_bfloat16 h0 = __float2bfloat16(w0);
        __nv_bfloat16 h1 = __float2bfloat16(w1);
        float l0 = w0 - __bfloat162float(h0);
        float l1 = w1 - __bfloat162float(h1);
        dst[cp]     = ((uint32_t)__bfloat16_as_ushort(h1) << 16) | __bfloat16_as_ushort(h0);
        dst[8 + cp] = pkbf(l0, l1);
    }
}

// ---------------- per-timestep kernel ----------------
__global__ __launch_bounds__(512)
void step_kernel(const float* __restrict__ x_t,     // [B,CIN,64,64]
                 const float* __restrict__ h_prev,  // [B,HID,64,64]
                 const float* __restrict__ b_x2h,
                 const float* __restrict__ b_h2h,
                 float* __restrict__ h_out,         // [B,HID,64,64]
                 int first)
{
    extern __shared__ unsigned char sm[];
    const uint32_t smb = s2u(sm);
    const int tid = threadIdx.x;
    const int wid = tid >> 5, lane = tid & 31;
    const int mi = wid & 3, ni = wid >> 2;     // warp tile: 32 px x 64 oc (gate ni)
    const int y0 = blockIdx.x * 2;
    const int b  = blockIdx.y;

    float* sbias = (float*)(sm + OFF_BIAS);
    if (tid < 256) sbias[tid] = b_x2h[tid] + b_h2h[tid];

    // per-lane ldmatrix base addresses
    const int idxl = lane & 7, q = lane >> 3;
    uint32_t baseA[2];
#pragma unroll
    for (int mt = 0; mt < 2; mt++) {
        int px = mi * 32 + mt * 16 + ((q & 1) << 3) + idxl;
        int arow = ((px >> 6) + 1) * 66 + (px & 63) + 1;
        baseA[mt] = smb + OFF_A + arow * 80 + ((q >> 1) << 4);
    }
    uint32_t baseB[4];
#pragma unroll
    for (int p = 0; p < 4; p++) {
        int oc = ni * 64 + p * 16 + ((q >> 1) << 3) + idxl;
        baseB[p] = oc * 80 + ((q & 1) << 4);
    }

    float acc[2][8][4];
#pragma unroll
    for (int mt = 0; mt < 2; mt++)
#pragma unroll
        for (int t8 = 0; t8 < 8; t8++)
#pragma unroll
            for (int k = 0; k < 4; k++) acc[mt][t8][k] = 0.f;

    const int NG = first ? 2 : 6;
    const int s_total = NG * 3;

    // group copy: 3 tiles (48 KB) per (icg, grp)
#define ISSUE_GRP(s_, buf_) do {                                                     \
    const char* gs0 = (const char*)g_B + ((size_t)(s_)) * (3 * 16384);               \
    _Pragma("unroll")                                                                \
    for (int k2 = 0; k2 < 6; k2++) {                                                 \
        int ii = tid + k2 * 512;                                                     \
        int tj = ii >> 10;                 /* tile 0..2 */                           \
        int cc2 = ii & 1023;                                                         \
        int oc_ = cc2 >> 2, j_ = cc2 & 3;                                            \
        uint32_t dsts = smb + OFF_B + (buf_) * GRP_SM + tj * TILE_SM + oc_ * 80 + j_ * 16; \
        asm volatile("cp.async.cg.shared.global [%0], [%1], 16;"                     \
                     :: "r"(dsts), "l"(gs0 + tj * 16384 + oc_ * 64 + j_ * 16) : "memory"); \
    }                                                                                \
    asm volatile("cp.async.commit_group;" ::: "memory");                             \
} while (0)

    ISSUE_GRP(0, 0);

    for (int s = 0; s < s_total; s++) {
        const int icg = s / 3, grp = s - icg * 3;
        if (grp == 0) {
            __syncthreads();   // all prior ldsm reads of A done
            // ---- fill A: 264 halo-padded pixel rows, 16 ch hi|lo ----
            const float* srcb = (icg < 2)
                ? x_t    + ((size_t)b * CIN + icg * 16) * HW
                : h_prev + ((size_t)b * HID + (icg - 2) * 16) * HW;
            for (int p = tid; p < 264; p += 512) {
                int rr = p / 66, cc = p - rr * 66;
                int r_img = y0 - 1 + rr;
                bool ok = (cc >= 1) && (cc <= 64) && ((unsigned)r_img < 64u);
                const float* gp = srcb + r_img * 64 + (cc - 1);
                uint32_t* dst = (uint32_t*)(sm + OFF_A + p * 80);
#pragma unroll
                for (int cp = 0; cp < 8; cp++) {
                    float v0 = ok ? gp[(2 * cp) * HW] : 0.f;
                    float v1 = ok ? gp[(2 * cp + 1) * HW] : 0.f;
                    __nv_bfloat16 h0 = __float2bfloat16(v0);
                    __nv_bfloat16 h1 = __float2bfloat16(v1);
                    float l0 = v0 - __bfloat162float(h0);
                    float l1 = v1 - __bfloat162float(h1);
                    dst[cp]     = ((uint32_t)__bfloat16_as_ushort(h1) << 16) | __bfloat16_as_ushort(h0);
                    dst[8 + cp] = pkbf(l0, l1);
                }
            }
        }

        asm volatile("cp.async.wait_group 0;" ::: "memory");
        __syncthreads();                       // B group visible; other buffer free; A visible
        if (s + 1 < s_total) ISSUE_GRP(s + 1, (s + 1) & 1);

        const int buf = s & 1;
#pragma unroll
        for (int t = 0; t < 3; t++) {
            const int tap = grp * 3 + t;
            const int dy = tap / 3 - 1, dx = tap % 3 - 1;
            const int ash = (dy * 66 + dx) * 80;
            unsigned ahi[2][4], alo[2][4];
            ldsm4(ahi[0], baseA[0] + ash);
            ldsm4(ahi[1], baseA[1] + ash);
            ldsm4(alo[0], baseA[0] + ash + 32);
            ldsm4(alo[1], baseA[1] + ash + 32);

            const uint32_t bb = smb + OFF_B + buf * GRP_SM + t * TILE_SM;
#pragma unroll
            for (int half = 0; half < 2; half++) {
                unsigned bh[2][4], bl[2][4];
                ldsm4(bh[0], bb + baseB[2 * half]);
                ldsm4(bh[1], bb + baseB[2 * half + 1]);
                ldsm4(bl[0], bb + baseB[2 * half] + 32);
                ldsm4(bl[1], bb + baseB[2 * half + 1] + 32);
                // term-outer: same-acc reuse distance = 8 MMAs (hides HMMA latency)
#pragma unroll
                for (int mt = 0; mt < 2; mt++)
#pragma unroll
                    for (int tt = 0; tt < 4; tt++)
                        mma16816(acc[mt][half * 4 + tt], ahi[mt], &bh[tt >> 1][(tt & 1) * 2]);
#pragma unroll
                for (int mt = 0; mt < 2; mt++)
#pragma unroll
                    for (int tt = 0; tt < 4; tt++)
                        mma16816(acc[mt][half * 4 + tt], alo[mt], &bh[tt >> 1][(tt & 1) * 2]);
#pragma unroll
                for (int mt = 0; mt < 2; mt++)
#pragma unroll
                    for (int tt = 0; tt < 4; tt++)
                        mma16816(acc[mt][half * 4 + tt], ahi[mt], &bl[tt >> 1][(tt & 1) * 2]);
            }
        }
    }

    // ---- store accumulators to gates smem ----
    __syncthreads();
    float* gates = (float*)(sm + OFF_GATES);
    {
        const int tg = lane >> 2, t4 = lane & 3;
#pragma unroll
        for (int mt = 0; mt < 2; mt++) {
#pragma unroll
            for (int t8 = 0; t8 < 8; t8++) {
                int px0 = mi * 32 + mt * 16 + tg;
                int oc0 = ni * 64 + t8 * 8 + t4 * 2;
                gates[px0 * GSTRIDE + oc0]           = acc[mt][t8][0];
                gates[px0 * GSTRIDE + oc0 + 1]       = acc[mt][t8][1];
                gates[(px0 + 8) * GSTRIDE + oc0]     = acc[mt][t8][2];
                gates[(px0 + 8) * GSTRIDE + oc0 + 1] = acc[mt][t8][3];
            }
        }
    }
    __syncthreads();

    // ---- LSTM pointwise ----
    for (int idx = tid; idx < 128 * 64; idx += 512) {
        const int hid = idx >> 7;
        const int px  = idx & 127;
        const int y = y0 + (px >> 6), x = px & 63;
        const float* gp = gates + px * GSTRIDE;
        float ai = gp[hid]       + sbias[hid];
        float af = gp[64 + hid]  + sbias[64 + hid];
        float ag = gp[128 + hid] + sbias[128 + hid];
        float ao = gp[192 + hid] + sbias[192 + hid];
        const size_t off = (((size_t)b * HID + hid) * 64 + y) * 64 + x;
        float gi = sigf(ai), gf = sigf(af), gg = tanhf(ag), go = sigf(ao);
        float cprev = first ? 0.f : g_c[off];
        float cn = gf * cprev + gi * gg;
        g_c[off]   = cn;
        h_out[off] = go * tanhf(cn);
    }
}

extern "C" void kernel_launch(void* const* d_in, const int* in_sizes, int n_in,
                              void* d_out, int out_size)
{
    const float* x     = (const float*)d_in[0];
    const float* w_x2h = (const float*)d_in[1];
    const float* b_x2h = (const float*)d_in[2];
    const float* w_h2h = (const float*)d_in[3];
    const float* b_h2h = (const float*)d_in[4];
    float* out = (float*)d_out;

    cudaFuncSetAttribute(step_kernel,
                         cudaFuncAttributeMaxDynamicSharedMemorySize, SMEM_TOTAL);

    prep_kernel<<<54, 256>>>(w_x2h, w_h2h);

    const size_t x_step = (size_t)B_ * CIN * HW;
    const size_t h_step = (size_t)B_ * HID * HW;
    dim3 grid(32, B_);
    for (int t = 0; t < T_; t++) {
        const float* x_t    = x + (size_t)t * x_step;
        const float* h_prev = (t == 0) ? x : out + (size_t)(t - 1) * h_step;
        float* h_out        = out + (size_t)t * h_step;
        step_kernel<<<grid, 512, SMEM_TOTAL>>>(x_t, h_prev, b_x2h, b_h2h,
                                               h_out, t == 0 ? 1 : 0);
    }
}

// round 14
// speedup vs baseline: 11.0405x; 1.0273x over previous
#include <cuda_runtime.h>
#include <cuda_bf16.h>
#include <math.h>
#include <stdint.h>

// ConvLSTM T=16,B=4,Cin=32,HID=64,H=W=64, 3x3 SAME — HMMA bf16 hi/lo split.
// R14: oc-split (N=128/CTA, hid-halves), 256 thr/CTA, 2 CTAs/SM co-residency.

#define T_ 16
#define B_ 4
#define CIN 32
#define HID 64
#define HW 4096

#define OFF_BIAS 0
#define OFF_A 1024
#define A_BYTES (264 * 80)            // 21120
#define OFF_B (OFF_A + A_BYTES)       // 22144
#define TILE_SM 10240                 // 128 loc-oc rows * 80B
#define GRP_SM (3 * TILE_SM)          // 30720
#define SMEM_TOTAL (OFF_B + 2 * GRP_SM)   // 83584
#define GSTRIDE 132
#define OFF_GATES 1024                // aliases A/B region post-compute

__device__ float g_c[B_ * HID * HW];                        // cell state (4 MB)
__device__ __align__(128) unsigned char g_B[54 * 16384];    // split weights (864 KB)

static __device__ __forceinline__ uint32_t s2u(const void* p) {
    uint32_t a;
    asm("{ .reg .u64 t; cvta.to.shared.u64 t, %1; cvt.u32.u64 %0, t; }" : "=r"(a) : "l"(p));
    return a;
}
static __device__ __forceinline__ void ldsm4(unsigned* r, uint32_t addr) {
    asm volatile("ldmatrix.sync.aligned.m8n8.x4.shared.b16 {%0,%1,%2,%3}, [%4];"
                 : "=r"(r[0]), "=r"(r[1]), "=r"(r[2]), "=r"(r[3]) : "r"(addr));
}
static __device__ __forceinline__ void mma16816(float* d, const unsigned* a, const unsigned* b) {
    asm volatile("mma.sync.aligned.m16n8k16.row.col.f32.bf16.bf16.f32 "
                 "{%0,%1,%2,%3}, {%4,%5,%6,%7}, {%8,%9}, {%0,%1,%2,%3};"
                 : "+f"(d[0]), "+f"(d[1]), "+f"(d[2]), "+f"(d[3])
                 : "r"(a[0]), "r"(a[1]), "r"(a[2]), "r"(a[3]), "r"(b[0]), "r"(b[1]));
}
static __device__ __forceinline__ float sigf(float x) {
    return 1.f / (1.f + __expf(-x));
}
static __device__ __forceinline__ uint32_t pkbf(float v0, float v1) {
    __nv_bfloat162 t = __floats2bfloat162_rn(v0, v1);
    return *(uint32_t*)&t;
}

// ---------------- weight prep: split fp32 -> bf16 hi/lo ----------------
// g_B tile (icg*9+tap): 256 oc rows x 64B: [0,32)=hi ch0..15, [32,64)=lo ch0..15
__global__ void prep_kernel(const float* __restrict__ w_x2h, const float* __restrict__ w_h2h) {
    const int icg = blockIdx.x / 9, tap = blockIdx.x % 9;
    const int oc = threadIdx.x;
    uint32_t* dst = (uint32_t*)(g_B + (size_t)blockIdx.x * 16384 + oc * 64);
#pragma unroll
    for (int cp = 0; cp < 8; cp++) {
        float w0, w1;
        if (icg < 2) {
            int ic = icg * 16 + 2 * cp;
            w0 = w_x2h[((size_t)oc * CIN + ic) * 9 + tap];
            w1 = w_x2h[((size_t)oc * CIN + ic + 1) * 9 + tap];
        } else {
            int ic = (icg - 2) * 16 + 2 * cp;
            w0 = w_h2h[((size_t)oc * HID + ic) * 9 + tap];
            w1 = w_h2h[((size_t)oc * HID + ic + 1) * 9 + tap];
        }
        __nv_bfloat16 h0 = __float2bfloat16(w0);
        __nv_bfloat16 h1 = __float2bfloat16(w1);
        float l0 = w0 - __bfloat162float(h0);
        float l1 = w1 - __bfloat162float(h1);
        dst[cp]     = ((uint32_t)__bfloat16_as_ushort(h1) << 16) | __bfloat16_as_ushort(h0);
        dst[8 + cp] = pkbf(l0, l1);
    }
}

// ---------------- per-timestep kernel ----------------
__global__ __launch_bounds__(256, 2)
void step_kernel(const float* __restrict__ x_t,     // [B,CIN,64,64]
                 const float* __restrict__ h_prev,  // [B,HID,64,64]
                 const float* __restrict__ b_x2h,
                 const float* __restrict__ b_h2h,
                 float* __restrict__ h_out,         // [B,HID,64,64]
                 int first)
{
    extern __shared__ unsigned char sm[];
    const uint32_t smb = s2u(sm);
    const int tid = threadIdx.x;
    const int wid = tid >> 5, lane = tid & 31;
    const int mi = wid & 3, ni = wid >> 2;     // warp: 32 px x 64 loc-oc (ni 0..1)
    const int y0 = blockIdx.x * 2;
    const int ocg = blockIdx.y;                 // hid half: 0 or 1
    const int b  = blockIdx.z;

    float* sbias = (float*)(sm + OFF_BIAS);
    sbias[tid] = b_x2h[tid] + b_h2h[tid];

    // per-lane ldmatrix base addresses
    const int idxl = lane & 7, q = lane >> 3;
    uint32_t baseA[2];
#pragma unroll
    for (int mt = 0; mt < 2; mt++) {
        int px = mi * 32 + mt * 16 + ((q & 1) << 3) + idxl;
        int arow = ((px >> 6) + 1) * 66 + (px & 63) + 1;
        baseA[mt] = smb + OFF_A + arow * 80 + ((q >> 1) << 4);
    }
    uint32_t baseB[4];
#pragma unroll
    for (int p = 0; p < 4; p++) {
        int loc = ni * 64 + p * 16 + ((q >> 1) << 3) + idxl;   // local oc row
        baseB[p] = loc * 80 + ((q & 1) << 4);
    }

    float acc[2][8][4];
#pragma unroll
    for (int mt = 0; mt < 2; mt++)
#pragma unroll
        for (int t8 = 0; t8 < 8; t8++)
#pragma unroll
            for (int k = 0; k < 4; k++) acc[mt][t8][k] = 0.f;

    const int NG = first ? 2 : 6;
    const int s_total = NG * 3;

    // group copy: 3 tiles, this CTA's 128 loc-oc rows (4 gates x 32 hid of ocg half)
#define ISSUE_GRP(s_, buf_) do {                                                     \
    const char* gs0 = (const char*)g_B + ((size_t)(s_)) * (3 * 16384);               \
    _Pragma("unroll")                                                                \
    for (int k2 = 0; k2 < 6; k2++) {                                                 \
        int ii = tid + k2 * 256;                                                     \
        int tj = ii >> 9;                  /* tile 0..2 */                           \
        int rr2 = ii & 511;                                                          \
        int loc_ = rr2 >> 2, j_ = rr2 & 3;                                           \
        int ocgl = (loc_ >> 5) * 64 + ocg * 32 + (loc_ & 31);                        \
        uint32_t dsts = smb + OFF_B + (buf_) * GRP_SM + tj * TILE_SM + loc_ * 80 + j_ * 16; \
        asm volatile("cp.async.cg.shared.global [%0], [%1], 16;"                     \
                     :: "r"(dsts), "l"(gs0 + tj * 16384 + ocgl * 64 + j_ * 16) : "memory"); \
    }                                                                                \
    asm volatile("cp.async.commit_group;" ::: "memory");                             \
} while (0)

    ISSUE_GRP(0, 0);

    for (int s = 0; s < s_total; s++) {
        const int icg = s / 3, grp = s - icg * 3;
        if (grp == 0) {
            __syncthreads();   // prior ldsm reads of A done
            // ---- fill A: 264 halo-padded pixel rows, 16 ch hi|lo ----
            const float* srcb = (icg < 2)
                ? x_t    + ((size_t)b * CIN + icg * 16) * HW
                : h_prev + ((size_t)b * HID + (icg - 2) * 16) * HW;
            for (int p = tid; p < 264; p += 256) {
                int rr = p / 66, cc = p - rr * 66;
                int r_img = y0 - 1 + rr;
                bool ok = (cc >= 1) && (cc <= 64) && ((unsigned)r_img < 64u);
                const float* gp = srcb + r_img * 64 + (cc - 1);
                uint32_t* dst = (uint32_t*)(sm + OFF_A + p * 80);
#pragma unroll
                for (int cp = 0; cp < 8; cp++) {
                    float v0 = ok ? gp[(2 * cp) * HW] : 0.f;
                    float v1 = ok ? gp[(2 * cp + 1) * HW] : 0.f;
                    __nv_bfloat16 h0 = __float2bfloat16(v0);
                    __nv_bfloat16 h1 = __float2bfloat16(v1);
                    float l0 = v0 - __bfloat162float(h0);
                    float l1 = v1 - __bfloat162float(h1);
                    dst[cp]     = ((uint32_t)__bfloat16_as_ushort(h1) << 16) | __bfloat16_as_ushort(h0);
                    dst[8 + cp] = pkbf(l0, l1);
                }
            }
        }

        asm volatile("cp.async.wait_group 0;" ::: "memory");
        __syncthreads();                       // B group visible; other buffer free; A visible
        if (s + 1 < s_total) ISSUE_GRP(s + 1, (s + 1) & 1);

        const int buf = s & 1;
#pragma unroll
        for (int t = 0; t < 3; t++) {
            const int tap = grp * 3 + t;
            const int dy = tap / 3 - 1, dx = tap % 3 - 1;
            const int ash = (dy * 66 + dx) * 80;
            unsigned ahi[2][4], alo[2][4];
            ldsm4(ahi[0], baseA[0] + ash);
            ldsm4(ahi[1], baseA[1] + ash);
            ldsm4(alo[0], baseA[0] + ash + 32);
            ldsm4(alo[1], baseA[1] + ash + 32);

            const uint32_t bb = smb + OFF_B + buf * GRP_SM + t * TILE_SM;
#pragma unroll
            for (int half = 0; half < 2; half++) {
                unsigned bh[2][4], bl[2][4];
                ldsm4(bh[0], bb + baseB[2 * half]);
                ldsm4(bh[1], bb + baseB[2 * half + 1]);
                ldsm4(bl[0], bb + baseB[2 * half] + 32);
                ldsm4(bl[1], bb + baseB[2 * half + 1] + 32);
#pragma unroll
                for (int mt = 0; mt < 2; mt++)
#pragma unroll
                    for (int tt = 0; tt < 4; tt++)
                        mma16816(acc[mt][half * 4 + tt], ahi[mt], &bh[tt >> 1][(tt & 1) * 2]);
#pragma unroll
                for (int mt = 0; mt < 2; mt++)
#pragma unroll
                    for (int tt = 0; tt < 4; tt++)
                        mma16816(acc[mt][half * 4 + tt], alo[mt], &bh[tt >> 1][(tt & 1) * 2]);
#pragma unroll
                for (int mt = 0; mt < 2; mt++)
#pragma unroll
                    for (int tt = 0; tt < 4; tt++)
                        mma16816(acc[mt][half * 4 + tt], ahi[mt], &bl[tt >> 1][(tt & 1) * 2]);
            }
        }
    }

    // ---- store accumulators to gates smem (aliases A/B region) ----
    __syncthreads();
    float* gates = (float*)(sm + OFF_GATES);
    {
        const int tg = lane >> 2, t4 = lane & 3;
#pragma unroll
        for (int mt = 0; mt < 2; mt++) {
#pragma unroll
            for (int t8 = 0; t8 < 8; t8++) {
                int px0 = mi * 32 + mt * 16 + tg;
                int loc0 = ni * 64 + t8 * 8 + t4 * 2;
                gates[px0 * GSTRIDE + loc0]           = acc[mt][t8][0];
                gates[px0 * GSTRIDE + loc0 + 1]       = acc[mt][t8][1];
                gates[(px0 + 8) * GSTRIDE + loc0]     = acc[mt][t8][2];
                gates[(px0 + 8) * GSTRIDE + loc0 + 1] = acc[mt][t8][3];
            }
        }
    }
    __syncthreads();

    // ---- LSTM pointwise (this CTA's 32 hids) ----
    for (int idx = tid; idx < 128 * 32; idx += 256) {
        const int hl = idx >> 7;            // 0..31
        const int px = idx & 127;
        const int hid = ocg * 32 + hl;
        const int y = y0 + (px >> 6), x = px & 63;
        const float* gp = gates + px * GSTRIDE;
        float ai = gp[hl]      + sbias[hid];
        float af = gp[32 + hl] + sbias[64 + hid];
        float ag = gp[64 + hl] + sbias[128 + hid];
        float ao = gp[96 + hl] + sbias[192 + hid];
        const size_t off = (((size_t)b * HID + hid) * 64 + y) * 64 + x;
        float gi = sigf(ai), gf = sigf(af), gg = tanhf(ag), go = sigf(ao);
        float cprev = first ? 0.f : g_c[off];
        float cn = gf * cprev + gi * gg;
        g_c[off]   = cn;
        h_out[off] = go * tanhf(cn);
    }
}

extern "C" void kernel_launch(void* const* d_in, const int* in_sizes, int n_in,
                              void* d_out, int out_size)
{
    const float* x     = (const float*)d_in[0];
    const float* w_x2h = (const float*)d_in[1];
    const float* b_x2h = (const float*)d_in[2];
    const float* w_h2h = (const float*)d_in[3];
    const float* b_h2h = (const float*)d_in[4];
    float* out = (float*)d_out;

    cudaFuncSetAttribute(step_kernel,
                         cudaFuncAttributeMaxDynamicSharedMemorySize, SMEM_TOTAL);

    prep_kernel<<<54, 256>>>(w_x2h, w_h2h);

    const size_t x_step = (size_t)B_ * CIN * HW;
    const size_t h_step = (size_t)B_ * HID * HW;
    dim3 grid(32, 2, B_);   // 32 y-tiles, 2 hid-halves, 4 batch
    for (int t = 0; t < T_; t++) {
        const float* x_t    = x + (size_t)t * x_step;
        const float* h_prev = (t == 0) ? x : out + (size_t)(t - 1) * h_step;
        float* h_out        = out + (size_t)t * h_step;
        step_kernel<<<grid, 256, SMEM_TOTAL>>>(x_t, h_prev, b_x2h, b_h2h,
                                               h_out, t == 0 ? 1 : 0);
    }
}